// round 12
// baseline (speedup 1.0000x reference)
#include <cuda_runtime.h>
#include <cuda_bf16.h>
#include <cstdint>

// BasicMFNet: embed_user [8192,64] f32, embed_item [16384,64] f32,
// indices [2,200000] (int32 or int64 — detected at runtime), ratings [200000] f32.
// Output: pred [U*I] | label [U*I] | ratio (1)  -- all float32.
constexpr int U = 8192;
constexpr int I = 16384;
constexpr int H = 64;

constexpr int TM = 128;          // tile rows (users)
constexpr int TN = 64;           // tile cols (items)
constexpr int NCOLF = I / TN;    // 256 column-tile flags
constexpr int NROWF = U / TM;    // 64 row-tile flags

__device__ int g_umask[U];
__device__ int g_imask[I];
__device__ int g_colflag[NCOLF];
__device__ int g_rowflag[NROWF];
__device__ int g_idx_is_i32;     // 1 if indices buffer is int32, 0 if int64

// ---------------------------------------------------------------------------
// Packed f32x2 helpers (Blackwell FFMA2 — PTX-only path, 2x fp32 FMA rate)
// ---------------------------------------------------------------------------
union U64F2 { unsigned long long u; float2 f; };

__device__ __forceinline__ unsigned long long dup_f32(float x) {
    unsigned long long r;
    unsigned xi = __float_as_uint(x);
    asm("mov.b64 %0, {%1, %1};" : "=l"(r) : "r"(xi));
    return r;
}
__device__ __forceinline__ void ffma2(unsigned long long& d,
                                      unsigned long long a,
                                      unsigned long long b) {
    asm("fma.rn.f32x2 %0, %1, %2, %0;" : "+l"(d) : "l"(a), "l"(b));
}

__device__ __forceinline__ void read_uv(const void* idx, int nnz, int t,
                                        int& u, int& v) {
    if (g_idx_is_i32) {
        const int* p = (const int*)idx;
        u = p[t];
        v = p[nnz + t];
    } else {
        const long long* p = (const long long*)idx;
        u = (int)p[t];
        v = (int)p[nnz + t];
    }
}

// ---------------------------------------------------------------------------
// Kernel 1: init — zero masks/flags; block 0 detects index dtype and writes
// the ratio output (depends on nothing else).
// ---------------------------------------------------------------------------
__global__ void k_init(const int* __restrict__ idx_w32, int n_words,
                       float* __restrict__ out, int nnz, long long out_size) {
    int t = blockIdx.x * blockDim.x + threadIdx.x;
    if (t < U) g_umask[t] = 0;
    if (t < I) g_imask[t] = 0;
    if (t < NCOLF) g_colflag[t] = 0;
    if (t < NROWF) g_rowflag[t] = 0;
    if (blockIdx.x == 0) {
        __shared__ int s_found;
        if (threadIdx.x == 0) s_found = 0;
        __syncthreads();
        int found = 0;
        for (int w = 2 * (int)threadIdx.x + 1; w < n_words; w += 2 * (int)blockDim.x)
            if (idx_w32[w] != 0) found = 1;
        if (found) s_found = 1;
        __syncthreads();
        if (threadIdx.x == 0) {
            g_idx_is_i32 = s_found;
            if (out_size > 2ll * U * I)
                out[2ull * U * I] = (float)(((double)U * (double)I) / (double)nnz);
        }
    }
}

// ---------------------------------------------------------------------------
// Kernel 2: set masks + tile flags from indices (bounds-guarded)
// ---------------------------------------------------------------------------
__global__ void k_set_masks(const void* __restrict__ idx, int nnz) {
    int t = blockIdx.x * blockDim.x + threadIdx.x;
    if (t >= nnz) return;
    int u, v;
    read_uv(idx, nnz, t, u, v);
    if (u >= 0 && u < U) { g_umask[u] = 1; g_rowflag[u >> 7] = 1; }
    if (v >= 0 && v < I) { g_imask[v] = 1; g_colflag[v >> 6] = 1; }
}

// ---------------------------------------------------------------------------
// Kernel 3: GEMM  pred = (masked eu) * (masked ei)^T.
// 128x64 tile, 256 threads, 3 CTAs/SM (24 warps: +50% concurrency vs the
// 2-CTA 128x128 version whose profile was phase-serialized at occ 22.5%).
// Warp = 16 rows x 64 cols; lane = (row-half rh, col-quad c4):
//   rows rowbase..rowbase+7 (rh selects 8-row half), cols c4*4..+3.
// Per k per warp: B = 1 LDS.128 (16 distinct addrs), A = 2 broadcast
// LDS.128, 4 dup-MOVs, 16 FFMA2/thread. acc = 16 u64 (~75 regs total,
// safely under the 85-reg cap of launch_bounds(256,3) -> no spill).
// Masks are applied in the load phase (build_scratch kernel eliminated).
// Epilogue stores pred + zero label tiles (fused; STG.128, coalesced).
// ---------------------------------------------------------------------------
__global__ void __launch_bounds__(256, 3) k_gemm(const float* __restrict__ eu,
                                                 const float* __restrict__ ei,
                                                 float* __restrict__ out) {
    const int bx = blockIdx.x;            // column tile (items), I/TN
    const int by = blockIdx.y;            // row tile (users),   U/TM
    const int m0 = by * TM;
    const int n0 = bx * TN;
    const int tid = threadIdx.x;
    const int wid = tid >> 5;             // 0..7
    const int lid = tid & 31;
    const int rh  = lid >> 4;             // row-half within warp's 16 rows
    const int c4  = lid & 15;             // col-quad
    const int rowbase = wid * 16 + rh * 8;  // 8 rows per lane-group
    const int col0    = c4 * 4;             // 4 cols per lane

    float* pred  = out;
    float* label = out + (size_t)U * I;

    const bool active = (g_rowflag[by] != 0) && (g_colflag[bx] != 0);

    if (!active) {
        const ulonglong2 z = make_ulonglong2(0ull, 0ull);
        #pragma unroll
        for (int r = 0; r < 8; r++) {
            size_t off = (size_t)(m0 + rowbase + r) * I + n0 + col0;
            *reinterpret_cast<ulonglong2*>(pred + off)  = z;
            *reinterpret_cast<ulonglong2*>(label + off) = z;
        }
        return;
    }

    __shared__ float As[H][TM];   // k-major A tile, 32 KB
    __shared__ float Bs[H][TN];   // k-major B tile, 16 KB

    // Load+mask+transpose. Lanes stride rows -> conflict-free STS.32.
    // A: 128 rows x 64 k = 2048 float4; B: 64 rows x 64 k = 1024 float4.
    #pragma unroll
    for (int it = 0; it < 8; it++) {
        int id = tid + it * 256;          // 0..2047
        int r = id & 127;
        int c = id >> 7;                  // 0..15 (k-group of 4)
        float4 va = *reinterpret_cast<const float4*>(
            &eu[(size_t)(m0 + r) * H + c * 4]);
        float um = g_umask[m0 + r] ? 1.0f : 0.0f;
        As[c * 4 + 0][r] = va.x * um;
        As[c * 4 + 1][r] = va.y * um;
        As[c * 4 + 2][r] = va.z * um;
        As[c * 4 + 3][r] = va.w * um;
    }
    #pragma unroll
    for (int it = 0; it < 4; it++) {
        int id = tid + it * 256;          // 0..1023
        int r = id & 63;
        int c = id >> 6;                  // 0..15 (k-group of 4)
        float4 vb = *reinterpret_cast<const float4*>(
            &ei[(size_t)(n0 + r) * H + c * 4]);
        float im = g_imask[n0 + r] ? 1.0f : 0.0f;
        Bs[c * 4 + 0][r] = vb.x * im;
        Bs[c * 4 + 1][r] = vb.y * im;
        Bs[c * 4 + 2][r] = vb.z * im;
        Bs[c * 4 + 3][r] = vb.w * im;
    }

    // acc[i][j]: row pair (rowbase+2i, rowbase+2i+1), col (col0+j). 16 u64.
    U64F2 acc[4][4];
    #pragma unroll
    for (int i = 0; i < 4; i++)
        #pragma unroll
        for (int j = 0; j < 4; j++) acc[i][j].u = 0ull;

    __syncthreads();

    #pragma unroll 8
    for (int k = 0; k < H; k++) {
        // A: 8 consecutive rows as 4 u64 pairs via 2 broadcast LDS.128.
        ulonglong2 ap0 = *reinterpret_cast<const ulonglong2*>(&As[k][rowbase]);
        ulonglong2 ap1 = *reinterpret_cast<const ulonglong2*>(&As[k][rowbase + 4]);
        // B: one LDS.128, 16 distinct addrs covering 256B (row = 64 floats).
        float4 bv = *reinterpret_cast<const float4*>(&Bs[k][col0]);
        unsigned long long bd0 = dup_f32(bv.x);
        unsigned long long bd1 = dup_f32(bv.y);
        unsigned long long bd2 = dup_f32(bv.z);
        unsigned long long bd3 = dup_f32(bv.w);

        unsigned long long ap[4] = {ap0.x, ap0.y, ap1.x, ap1.y};
        #pragma unroll
        for (int i = 0; i < 4; i++) {
            ffma2(acc[i][0].u, ap[i], bd0);
            ffma2(acc[i][1].u, ap[i], bd1);
            ffma2(acc[i][2].u, ap[i], bd2);
            ffma2(acc[i][3].u, ap[i], bd3);
        }
    }

    // Epilogue: store pred + zero label. 16 lanes x 16B cover a full 256B
    // row; two rows per step (rh halves) -> coalesced STG.128.
    const ulonglong2 z = make_ulonglong2(0ull, 0ull);
    #pragma unroll
    for (int i = 0; i < 4; i++) {
        size_t off0 = (size_t)(m0 + rowbase + 2 * i) * I + n0 + col0;
        size_t off1 = off0 + I;
        float4 p0 = make_float4(acc[i][0].f.x, acc[i][1].f.x,
                                acc[i][2].f.x, acc[i][3].f.x);
        float4 p1 = make_float4(acc[i][0].f.y, acc[i][1].f.y,
                                acc[i][2].f.y, acc[i][3].f.y);
        *reinterpret_cast<float4*>(pred + off0) = p0;
        *reinterpret_cast<float4*>(pred + off1) = p1;
        *reinterpret_cast<ulonglong2*>(label + off0) = z;
        *reinterpret_cast<ulonglong2*>(label + off1) = z;
    }
}

// ---------------------------------------------------------------------------
// Kernel 4: scatter-add ratings into label (bounds-guarded)
// ---------------------------------------------------------------------------
__global__ void k_scatter(const void* __restrict__ idx,
                          const float* __restrict__ ratings,
                          float* __restrict__ out, int nnz) {
    int t = blockIdx.x * blockDim.x + threadIdx.x;
    if (t >= nnz) return;
    int u, v;
    read_uv(idx, nnz, t, u, v);
    if (u < 0 || u >= U || v < 0 || v >= I) return;
    float* label = out + (size_t)U * I;
    atomicAdd(&label[(size_t)u * I + v], ratings[t]);
}

// ---------------------------------------------------------------------------
extern "C" void kernel_launch(void* const* d_in, const int* in_sizes, int n_in,
                              void* d_out, int out_size) {
    const float* eu = (const float*)d_in[0];
    const float* ei = (const float*)d_in[1];
    const void*  idx = d_in[2];
    const float* ratings = (const float*)d_in[3];
    float* out = (float*)d_out;
    const int nnz = in_sizes[3];            // ratings count
    const int n_words = in_sizes[2] < 4096 ? in_sizes[2] : 4096;

    // 1. zero masks/flags + detect index dtype + ratio
    k_init<<<(I + 255) / 256, 256>>>((const int*)idx, n_words, out, nnz,
                                     (long long)out_size);
    // 2. set masks/flags from indices
    k_set_masks<<<(nnz + 255) / 256, 256>>>(idx, nnz);
    // 3. GEMM (masks applied in-load; writes pred + zeros label)
    {
        dim3 grid(I / TN, U / TM);
        k_gemm<<<grid, 256>>>(eu, ei, out);
    }
    // 4. scatter ratings into label
    k_scatter<<<(nnz + 255) / 256, 256>>>(idx, ratings, out, nnz);
}

// round 13
// speedup vs baseline: 1.4404x; 1.4404x over previous
#include <cuda_runtime.h>
#include <cuda_bf16.h>
#include <cstdint>

// BasicMFNet: embed_user [8192,64] f32, embed_item [16384,64] f32,
// indices [2,200000] (int32 or int64 — detected at runtime), ratings [200000] f32.
// Output: pred [U*I] | label [U*I] | ratio (1)  -- all float32.
constexpr int U = 8192;
constexpr int I = 16384;
constexpr int H = 64;

constexpr int TILE = 128;        // M and N tile
constexpr int NCOLF = I / TILE;  // 128 column-tile flags
constexpr int NROWF = U / TILE;  // 64 row-tile flags

// Device scratch (no allocations). All are zero at module load; k_scatter
// re-zeroes masks/flags at the end of every launch, so each launch starts
// from the same clean state (deterministic across graph replays).
__device__ float g_eu[U * H];     // masked user embeddings
__device__ float g_ei[I * H];     // masked item embeddings
__device__ int   g_umask[U];
__device__ int   g_imask[I];
__device__ int   g_colflag[NCOLF];
__device__ int   g_rowflag[NROWF];

// ---------------------------------------------------------------------------
// Packed f32x2 helpers (Blackwell FFMA2 — PTX-only path, 2x fp32 FMA rate)
// ---------------------------------------------------------------------------
union U64F2 { unsigned long long u; float2 f; };

__device__ __forceinline__ unsigned long long dup_f32(float x) {
    unsigned long long r;
    unsigned xi = __float_as_uint(x);
    asm("mov.b64 %0, {%1, %1};" : "=l"(r) : "r"(xi));
    return r;
}
__device__ __forceinline__ void ffma2(unsigned long long& d,
                                      unsigned long long a,
                                      unsigned long long b) {
    asm("fma.rn.f32x2 %0, %1, %2, %0;" : "+l"(d) : "l"(a), "l"(b));
}

// Block-local index-dtype detection: int64 values < 2^31 have every odd
// int32 word == 0; genuine int32 index data can't have 2048 zero odd words.
// Every block computes the same verdict from the same L2-hot 16 KB sample.
__device__ __forceinline__ int detect_i32_block(const int* idx_w32) {
    __shared__ int s_found;
    if (threadIdx.x == 0) s_found = 0;
    __syncthreads();
    int found = 0;
    for (int w = 2 * (int)threadIdx.x + 1; w < 4096; w += 2 * (int)blockDim.x)
        if (idx_w32[w] != 0) found = 1;
    if (found) s_found = 1;
    __syncthreads();
    return s_found;
}

__device__ __forceinline__ void read_uv_d(const void* idx, int nnz, int t,
                                          int is_i32, int& u, int& v) {
    if (is_i32) {
        const int* p = (const int*)idx;
        u = p[t];
        v = p[nnz + t];
    } else {
        const long long* p = (const long long*)idx;
        u = (int)p[t];
        v = (int)p[nnz + t];
    }
}

// ---------------------------------------------------------------------------
// Kernel 1: set masks + tile flags from indices (4 entries/thread, bounds-
// guarded). Masks/flags were zeroed by the previous launch's scatter (or by
// static init on the very first run). Block 0 also writes the ratio output.
// ---------------------------------------------------------------------------
__global__ void k_set_masks(const void* __restrict__ idx, int nnz,
                            float* __restrict__ out, long long out_size) {
    const int is_i32 = detect_i32_block((const int*)idx);
    int base = (blockIdx.x * blockDim.x + threadIdx.x) * 4;
    #pragma unroll
    for (int j = 0; j < 4; j++) {
        int t = base + j;
        if (t >= nnz) break;
        int u, v;
        read_uv_d(idx, nnz, t, is_i32, u, v);
        if (u >= 0 && u < U) { g_umask[u] = 1; g_rowflag[u >> 7] = 1; }
        if (v >= 0 && v < I) { g_imask[v] = 1; g_colflag[v >> 7] = 1; }
    }
    if (blockIdx.x == 0 && threadIdx.x == 0 && out_size > 2ll * U * I)
        out[2ull * U * I] = (float)(((double)U * (double)I) / (double)nnz);
}

// ---------------------------------------------------------------------------
// Kernel 2: build masked embedding copies
// ---------------------------------------------------------------------------
__global__ void k_build_scratch(const float* __restrict__ eu,
                                const float* __restrict__ ei) {
    int t = blockIdx.x * blockDim.x + threadIdx.x;
    const int NU4 = U * (H / 4);
    const int NI4 = I * (H / 4);
    if (t < NU4) {
        int row = t / (H / 4);
        float4 v = reinterpret_cast<const float4*>(eu)[t];
        if (!g_umask[row]) v = make_float4(0.f, 0.f, 0.f, 0.f);
        reinterpret_cast<float4*>(g_eu)[t] = v;
    } else if (t < NU4 + NI4) {
        int t2 = t - NU4;
        int row = t2 / (H / 4);
        float4 v = reinterpret_cast<const float4*>(ei)[t2];
        if (!g_imask[row]) v = make_float4(0.f, 0.f, 0.f, 0.f);
        reinterpret_cast<float4*>(g_ei)[t2] = v;
    }
}

// ---------------------------------------------------------------------------
// Kernel 3: GEMM  pred = g_eu * g_ei^T.  (byte-identical to R11's k_gemm)
// 128x128 tile, 256 threads. Warp w owns rows 16w..16w+15, lane l owns cols
// 4l..4l+3. Per k per warp: B = 1 LDS.128 all-distinct (4 wf), A = 4
// broadcast LDS.128 (~4 wf); 32 FFMA2/thread/k. Whole H=64 in smem, single
// sync. Epilogue stores pred + zero label tiles (fused, STG.128 coalesced).
// ---------------------------------------------------------------------------
__global__ void __launch_bounds__(256, 2) k_gemm(float* __restrict__ out) {
    const int bx = blockIdx.x;            // column tile (items)
    const int by = blockIdx.y;            // row tile (users)
    const int m0 = by * TILE;
    const int n0 = bx * TILE;
    const int tid = threadIdx.x;
    const int wid = tid >> 5;             // 0..7
    const int lid = tid & 31;
    const int rows0 = wid * 16;           // 16 rows per warp
    const int col0  = lid * 4;            // 4 cols per lane

    float* pred  = out;
    float* label = out + (size_t)U * I;

    const bool active = (g_rowflag[by] != 0) && (g_colflag[bx] != 0);

    if (!active) {
        const ulonglong2 z = make_ulonglong2(0ull, 0ull);
        #pragma unroll
        for (int r = 0; r < 16; r++) {
            size_t off = (size_t)(m0 + rows0 + r) * I + n0 + col0;
            *reinterpret_cast<ulonglong2*>(pred + off)  = z;
            *reinterpret_cast<ulonglong2*>(label + off) = z;
        }
        return;
    }

    __shared__ float As[H][TILE];   // k-major (transposed) tiles, 32 KB each
    __shared__ float Bs[H][TILE];

    #pragma unroll
    for (int it = 0; it < 8; it++) {
        int id = tid + it * 256;          // 0..2047
        int r = id & 127;
        int c = id >> 7;                  // 0..15 (k-group of 4)
        float4 va = *reinterpret_cast<const float4*>(
            &g_eu[(size_t)(m0 + r) * H + c * 4]);
        As[c * 4 + 0][r] = va.x;
        As[c * 4 + 1][r] = va.y;
        As[c * 4 + 2][r] = va.z;
        As[c * 4 + 3][r] = va.w;
        float4 vb = *reinterpret_cast<const float4*>(
            &g_ei[(size_t)(n0 + r) * H + c * 4]);
        Bs[c * 4 + 0][r] = vb.x;
        Bs[c * 4 + 1][r] = vb.y;
        Bs[c * 4 + 2][r] = vb.z;
        Bs[c * 4 + 3][r] = vb.w;
    }

    // acc[i][j]: row pair (rows0+2i, rows0+2i+1), col (col0+j). 32 u64.
    U64F2 acc[8][4];
    #pragma unroll
    for (int i = 0; i < 8; i++)
        #pragma unroll
        for (int j = 0; j < 4; j++) acc[i][j].u = 0ull;

    __syncthreads();

    #pragma unroll 8
    for (int k = 0; k < H; k++) {
        ulonglong2 ap0 = *reinterpret_cast<const ulonglong2*>(&As[k][rows0 + 0]);
        ulonglong2 ap1 = *reinterpret_cast<const ulonglong2*>(&As[k][rows0 + 4]);
        ulonglong2 ap2 = *reinterpret_cast<const ulonglong2*>(&As[k][rows0 + 8]);
        ulonglong2 ap3 = *reinterpret_cast<const ulonglong2*>(&As[k][rows0 + 12]);
        float4 bv = *reinterpret_cast<const float4*>(&Bs[k][col0]);
        unsigned long long bd0 = dup_f32(bv.x);
        unsigned long long bd1 = dup_f32(bv.y);
        unsigned long long bd2 = dup_f32(bv.z);
        unsigned long long bd3 = dup_f32(bv.w);

        unsigned long long ap[8] = {ap0.x, ap0.y, ap1.x, ap1.y,
                                    ap2.x, ap2.y, ap3.x, ap3.y};
        #pragma unroll
        for (int i = 0; i < 8; i++) {
            ffma2(acc[i][0].u, ap[i], bd0);
            ffma2(acc[i][1].u, ap[i], bd1);
            ffma2(acc[i][2].u, ap[i], bd2);
            ffma2(acc[i][3].u, ap[i], bd3);
        }
    }

    const ulonglong2 z = make_ulonglong2(0ull, 0ull);
    #pragma unroll
    for (int i = 0; i < 8; i++) {
        size_t off0 = (size_t)(m0 + rows0 + 2 * i) * I + n0 + col0;
        size_t off1 = off0 + I;
        float4 p0 = make_float4(acc[i][0].f.x, acc[i][1].f.x,
                                acc[i][2].f.x, acc[i][3].f.x);
        float4 p1 = make_float4(acc[i][0].f.y, acc[i][1].f.y,
                                acc[i][2].f.y, acc[i][3].f.y);
        *reinterpret_cast<float4*>(pred + off0) = p0;
        *reinterpret_cast<float4*>(pred + off1) = p1;
        *reinterpret_cast<ulonglong2*>(label + off0) = z;
        *reinterpret_cast<ulonglong2*>(label + off1) = z;
    }
}

// ---------------------------------------------------------------------------
// Kernel 4: scatter-add ratings into label (4 entries/thread, bounds-guarded)
// + cleanup: re-zero masks/flags for the next launch. Scatter never reads
// masks/flags and the GEMM (previous kernel) has completed, so any thread
// may zero any word at any time during this kernel.
// ---------------------------------------------------------------------------
__global__ void k_scatter(const void* __restrict__ idx,
                          const float* __restrict__ ratings,
                          float* __restrict__ out, int nnz) {
    const int is_i32 = detect_i32_block((const int*)idx);
    float* label = out + (size_t)U * I;
    int gtid = blockIdx.x * blockDim.x + threadIdx.x;
    int base = gtid * 4;
    #pragma unroll
    for (int j = 0; j < 4; j++) {
        int t = base + j;
        if (t >= nnz) break;
        int u, v;
        read_uv_d(idx, nnz, t, is_i32, u, v);
        if (u < 0 || u >= U || v < 0 || v >= I) continue;
        atomicAdd(&label[(size_t)u * I + v], ratings[t]);
    }
    // Cleanup for next launch: zero masks + flags (U + I + NCOLF + NROWF
    // ints = 24768 words; far fewer than the 200k threads here).
    if (gtid < U) g_umask[gtid] = 0;
    if (gtid < I) g_imask[gtid] = 0;
    if (gtid < NCOLF) g_colflag[gtid] = 0;
    if (gtid < NROWF) g_rowflag[gtid] = 0;
}

// ---------------------------------------------------------------------------
extern "C" void kernel_launch(void* const* d_in, const int* in_sizes, int n_in,
                              void* d_out, int out_size) {
    const float* eu = (const float*)d_in[0];
    const float* ei = (const float*)d_in[1];
    const void*  idx = d_in[2];
    const float* ratings = (const float*)d_in[3];
    float* out = (float*)d_out;
    const int nnz = in_sizes[3];            // ratings count

    // 1. set masks/flags (+dtype detect per block, +ratio)
    {
        int blocks = (nnz + 1023) / 1024;   // 4 entries/thread, 256 threads
        k_set_masks<<<blocks, 256>>>(idx, nnz, out, (long long)out_size);
    }
    // 2. masked embedding copies
    {
        int total = U * (H / 4) + I * (H / 4);
        k_build_scratch<<<(total + 255) / 256, 256>>>(eu, ei);
    }
    // 3. GEMM (writes pred + zeros label)
    {
        dim3 grid(I / TILE, U / TILE);
        k_gemm<<<grid, 256>>>(out);
    }
    // 4. scatter ratings into label + cleanup masks/flags for next launch
    {
        int blocks = (nnz + 1023) / 1024;
        k_scatter<<<blocks, 256>>>(idx, ratings, out, nnz);
    }
}

// round 16
// speedup vs baseline: 1.5168x; 1.0530x over previous
#include <cuda_runtime.h>
#include <cuda_bf16.h>
#include <cstdint>

// BasicMFNet: embed_user [8192,64] f32, embed_item [16384,64] f32,
// indices [2,200000] (int32 or int64 — detected at runtime), ratings [200000] f32.
// Output: pred [U*I] | label [U*I] | ratio (1)  -- all float32.
constexpr int U = 8192;
constexpr int I = 16384;
constexpr int H = 64;

constexpr int TILE = 128;        // M and N tile
constexpr int NCOLF = I / TILE;  // 128 column-tile flags
constexpr int NROWF = U / TILE;  // 64 row-tile flags

// Device scratch (no allocations). Zero at module load; k_scatter re-zeroes
// masks/flags at the end of every launch, so each launch starts clean
// (deterministic across graph replays).
__device__ int g_umask[U];
__device__ int g_imask[I];
__device__ int g_colflag[NCOLF];
__device__ int g_rowflag[NROWF];

// ---------------------------------------------------------------------------
// Packed f32x2 helpers (Blackwell FFMA2 — PTX-only path, 2x fp32 FMA rate)
// ---------------------------------------------------------------------------
__device__ __forceinline__ unsigned long long dup_f32(float x) {
    unsigned long long r;
    unsigned xi = __float_as_uint(x);
    asm("mov.b64 %0, {%1, %1};" : "=l"(r) : "r"(xi));
    return r;
}
__device__ __forceinline__ void ffma2(unsigned long long& d,
                                      unsigned long long a,
                                      unsigned long long b) {
    asm("fma.rn.f32x2 %0, %1, %2, %0;" : "+l"(d) : "l"(a), "l"(b));
}

// Block-local index-dtype detection: int64 values < 2^31 have every odd
// int32 word == 0; genuine int32 index data can't have 2048 zero odd words.
__device__ __forceinline__ int detect_i32_block(const int* w) {
    __shared__ int s_found;
    if (threadIdx.x == 0) s_found = 0;
    __syncthreads();
    int found = 0;
    for (int i = 2 * (int)threadIdx.x + 1; i < 4096; i += 2 * (int)blockDim.x)
        if (w[i] != 0) found = 1;
    if (found) s_found = 1;
    __syncthreads();
    return s_found;
}
__device__ __forceinline__ void read_uv_d(const void* idx, int nnz, int t,
                                          int is_i32, int& u, int& v) {
    if (is_i32) {
        const int* p = (const int*)idx;
        u = p[t]; v = p[nnz + t];
    } else {
        const long long* p = (const long long*)idx;
        u = (int)p[t]; v = (int)p[nnz + t];
    }
}

// ---------------------------------------------------------------------------
// Kernel 1: set masks + tile flags from indices (1 entry/thread, bounds-
// guarded). Masks/flags were zeroed by the previous launch's scatter (or
// static init on the first run). Block 0 thread 0 writes the ratio output.
// ---------------------------------------------------------------------------
__global__ void k_set_masks(const void* __restrict__ idx, int nnz,
                            float* __restrict__ out, long long out_size) {
    const int is_i32 = detect_i32_block((const int*)idx);
    int t = blockIdx.x * blockDim.x + threadIdx.x;
    if (t < nnz) {
        int u, v;
        read_uv_d(idx, nnz, t, is_i32, u, v);
        if (u >= 0 && u < U) { g_umask[u] = 1; g_rowflag[u >> 7] = 1; }
        if (v >= 0 && v < I) { g_imask[v] = 1; g_colflag[v >> 7] = 1; }
    }
    if (blockIdx.x == 0 && threadIdx.x == 0 && out_size > 2ll * U * I)
        out[2ull * U * I] = (float)(((double)U * (double)I) / (double)nnz);
}

// ---------------------------------------------------------------------------
// Kernel 2: GEMM  pred = (masked eu) * (masked ei)^T.
// Exactly R7's 264us GEMM (128x128 tile, 256 threads, 8x8 microtile split
// (4+4)x(4+4) at stride 64, whole H=64 in smem, single sync), with ONE
// change: masks are applied during the smem load phase (mask arrays are
// L2-resident; the separate masked-copy kernel and its 6 MB round trip are
// deleted). R7 used 110 regs — 18 regs of headroom under the 128 cap, so
// the transient mask loads cannot force spills (unlike the capped R8/R12).
// Epilogue zero-fills the matching label tile (fused with pred stores).
// ---------------------------------------------------------------------------
__global__ void __launch_bounds__(256, 2) k_gemm(const float* __restrict__ eu,
                                                 const float* __restrict__ ei,
                                                 float* __restrict__ out) {
    const int bx = blockIdx.x;            // column tile (items)
    const int by = blockIdx.y;            // row tile (users)
    const int m0 = by * TILE;
    const int n0 = bx * TILE;
    const int tid = threadIdx.x;
    const int tm4a = (tid >> 4) * 4;      // 16 row-groups of 4
    const int tn4a = (tid & 15) * 4;      // 16 col-groups of 4 (consecutive 16B)

    float* pred  = out;
    float* label = out + (size_t)U * I;

    const bool active = (g_rowflag[by] != 0) && (g_colflag[bx] != 0);

    if (!active) {
        const ulonglong2 z = make_ulonglong2(0ull, 0ull);
        #pragma unroll
        for (int i = 0; i < 8; i++) {
            int row = m0 + (i < 4 ? tm4a + i : 64 + tm4a + (i - 4));
            size_t off = (size_t)row * I + n0 + tn4a;
            *reinterpret_cast<ulonglong2*>(pred + off)       = z;
            *reinterpret_cast<ulonglong2*>(pred + off + 64)  = z;
            *reinterpret_cast<ulonglong2*>(label + off)      = z;
            *reinterpret_cast<ulonglong2*>(label + off + 64) = z;
        }
        return;
    }

    __shared__ float As[H][TILE];   // k-major (transposed) tiles, 32 KB each
    __shared__ float Bs[H][TILE];

    // Single load phase: 128 rows x 64 k per tile; lanes stride rows ->
    // conflict-free STS.32 (bank = r). Mask applied as a float multiply.
    #pragma unroll
    for (int it = 0; it < 8; it++) {
        int id = tid + it * 256;          // 0..2047
        int r = id & 127;
        int c = id >> 7;                  // 0..15 (k-group of 4)
        float4 va = *reinterpret_cast<const float4*>(
            &eu[(size_t)(m0 + r) * H + c * 4]);
        float um = g_umask[m0 + r] ? 1.0f : 0.0f;
        As[c * 4 + 0][r] = va.x * um;
        As[c * 4 + 1][r] = va.y * um;
        As[c * 4 + 2][r] = va.z * um;
        As[c * 4 + 3][r] = va.w * um;
        float4 vb = *reinterpret_cast<const float4*>(
            &ei[(size_t)(n0 + r) * H + c * 4]);
        float im = g_imask[n0 + r] ? 1.0f : 0.0f;
        Bs[c * 4 + 0][r] = vb.x * im;
        Bs[c * 4 + 1][r] = vb.y * im;
        Bs[c * 4 + 2][r] = vb.z * im;
        Bs[c * 4 + 3][r] = vb.w * im;
    }

    unsigned long long acc[8][4];    // [row][col-pair]
    #pragma unroll
    for (int i = 0; i < 8; i++)
        #pragma unroll
        for (int j = 0; j < 4; j++) acc[i][j] = 0ull;

    __syncthreads();

    #pragma unroll 8
    for (int k = 0; k < H; k++) {
        // A: 16B broadcast loads (2 distinct addrs/warp -> ~free)
        float4 a0 = *reinterpret_cast<const float4*>(&As[k][tm4a]);
        float4 a1 = *reinterpret_cast<const float4*>(&As[k][tm4a + 64]);
        // B: lanes 0-15 read consecutive 16B chunks (bytes 0..255) ->
        // conflict-free; lanes 16-31 broadcast the same addrs.
        ulonglong2 b0 = *reinterpret_cast<const ulonglong2*>(&Bs[k][tn4a]);
        ulonglong2 b1 = *reinterpret_cast<const ulonglong2*>(&Bs[k][tn4a + 64]);
        unsigned long long bp0 = b0.x, bp1 = b0.y, bp2 = b1.x, bp3 = b1.y;
        float av[8] = {a0.x, a0.y, a0.z, a0.w, a1.x, a1.y, a1.z, a1.w};
        #pragma unroll
        for (int i = 0; i < 8; i++) {
            unsigned long long ad = dup_f32(av[i]);
            ffma2(acc[i][0], ad, bp0);
            ffma2(acc[i][1], ad, bp1);
            ffma2(acc[i][2], ad, bp2);
            ffma2(acc[i][3], ad, bp3);
        }
    }

    // Epilogue: store pred tile + zero label tile. Lanes 0-15 of a warp cover
    // 256 consecutive bytes per row-chunk -> fully coalesced STG.128.
    const ulonglong2 z = make_ulonglong2(0ull, 0ull);
    #pragma unroll
    for (int i = 0; i < 8; i++) {
        int row = m0 + (i < 4 ? tm4a + i : 64 + tm4a + (i - 4));
        size_t off = (size_t)row * I + n0 + tn4a;
        *reinterpret_cast<ulonglong2*>(pred + off) =
            make_ulonglong2(acc[i][0], acc[i][1]);
        *reinterpret_cast<ulonglong2*>(pred + off + 64) =
            make_ulonglong2(acc[i][2], acc[i][3]);
        *reinterpret_cast<ulonglong2*>(label + off)      = z;
        *reinterpret_cast<ulonglong2*>(label + off + 64) = z;
    }
}

// ---------------------------------------------------------------------------
// Kernel 3: scatter-add ratings into label (4 entries/thread — measured
// faster than 1/thread: 11.4us vs 15us) + re-zero masks/flags for the next
// launch (scatter never reads masks; the GEMM has already consumed them).
// ---------------------------------------------------------------------------
__global__ void k_scatter(const void* __restrict__ idx,
                          const float* __restrict__ ratings,
                          float* __restrict__ out, int nnz) {
    const int is_i32 = detect_i32_block((const int*)idx);
    float* label = out + (size_t)U * I;
    int gtid = blockIdx.x * blockDim.x + threadIdx.x;
    int base = gtid * 4;
    #pragma unroll
    for (int j = 0; j < 4; j++) {
        int t = base + j;
        if (t >= nnz) break;
        int u, v;
        read_uv_d(idx, nnz, t, is_i32, u, v);
        if (u < 0 || u >= U || v < 0 || v >= I) continue;
        atomicAdd(&label[(size_t)u * I + v], ratings[t]);
    }
    // Cleanup for next launch (24768 words total; grid has ~50k threads).
    if (gtid < U) g_umask[gtid] = 0;
    if (gtid < I) g_imask[gtid] = 0;
    if (gtid < NCOLF) g_colflag[gtid] = 0;
    if (gtid < NROWF) g_rowflag[gtid] = 0;
}

// ---------------------------------------------------------------------------
extern "C" void kernel_launch(void* const* d_in, const int* in_sizes, int n_in,
                              void* d_out, int out_size) {
    const float* eu = (const float*)d_in[0];
    const float* ei = (const float*)d_in[1];
    const void*  idx = d_in[2];
    const float* ratings = (const float*)d_in[3];
    float* out = (float*)d_out;
    const int nnz = in_sizes[3];

    // 1. masks + flags + ratio
    k_set_masks<<<(nnz + 255) / 256, 256>>>(idx, nnz, out, (long long)out_size);
    // 2. GEMM (masks applied in-load; writes pred + zeros label)
    {
        dim3 grid(I / TILE, U / TILE);
        k_gemm<<<grid, 256>>>(eu, ei, out);
    }
    // 3. scatter ratings + cleanup masks/flags for next launch
    {
        int blocks = (nnz + 1023) / 1024;
        k_scatter<<<blocks, 256>>>(idx, ratings, out, nnz);
    }
}